// round 8
// baseline (speedup 1.0000x reference)
#include <cuda_runtime.h>
#include <cuda_fp16.h>
#include <cstdint>

// Problem constants (fixed by the dataset)
#define N_NODES 100000
#define N_EDGES 3200000
#define DIM     64
#define EPS     1e-16f

// ELL row capacity. Destination in-degree ~ Binomial(3.2M, 1e-5) ~ Poisson(32);
// P(deg >= 112) ~ e^-60 per node -- statistically impossible. Row stride
// 112 * 8B = 896B (128B-aligned).
#define MAXDEG  112

// ---------------- device scratch (static globals: allocation-free) ----------
__device__ float  g_in_sum[N_NODES];        // sum exp(l) over incoming edges (by to_)
__device__ float  g_out_sum[N_NODES];       // sum exp(l) over outgoing edges (by from_)
__device__ float  g_rin[N_NODES];           // rsqrt(in_sum + eps)  per node
__device__ float  g_rout[N_NODES];          // rsqrt(out_sum + eps) per node
__device__ int    g_deg[N_NODES];           // in-degree (by to_)
__device__ int2   g_ell[(size_t)N_NODES * MAXDEG];  // {src, exp(l)_bits} padded rows
__device__ __half g_buf0[(size_t)N_NODES * DIM];    // fp16 prescaled emb (c_f * emb)
__device__ __half g_bufA[(size_t)N_NODES * DIM];    // fp16 intermediates (c_t * y)
__device__ __half g_bufB[(size_t)N_NODES * DIM];

// ---------------- kernels ----------------------------------------------------

// SINGLE fused edge pass: softmax exp-sums for both directions + in-degree
// histogram + direct ELL placement of {src, exp(l)}. No second edge pass,
// no scan, no rank array. Max-subtraction dropped: logits ~ N(0,1), exp()
// cannot overflow; only difference vs reference is the 1e-16 eps scaling.
__global__ void k_edge_build(const int* __restrict__ ei, const float* __restrict__ attr) {
    int e = blockIdx.x * blockDim.x + threadIdx.x;
    if (e >= N_EDGES) return;
    int f = __ldcs(&ei[e]);
    int t = __ldcs(&ei[e + N_EDGES]);
    float el = __expf(__ldcs(&attr[e]));    // s_temp = 1.0
    atomicAdd(&g_in_sum[t],  el);
    atomicAdd(&g_out_sum[f], el);
    int rank = atomicAdd(&g_deg[t], 1);
    if (rank < MAXDEG)                       // impossible overflow guard
        g_ell[(size_t)t * MAXDEG + rank] = make_int2(f, __float_as_int(el));
}

// Per-node reciprocal square roots of the softmax denominators.
__global__ void k_rcp() {
    int i = blockIdx.x * blockDim.x + threadIdx.x;
    if (i >= N_NODES) return;
    g_rin[i]  = rsqrtf(g_in_sum[i]  + EPS);
    g_rout[i] = rsqrtf(g_out_sum[i] + EPS);
}

// Prescale: out = emb (tuple element 0) and buf0 = fp16(c_f * emb) in one pass.
__global__ void k_prescale(const float* __restrict__ emb, float* __restrict__ out) {
    int o = blockIdx.x * blockDim.x + threadIdx.x;          // float2 index
    if (o >= N_NODES * 32) return;
    int n = o >> 5;
    float c = g_rout[n];                                    // broadcast within row
    float2 v = reinterpret_cast<const float2*>(emb)[o];
    reinterpret_cast<float2*>(out)[o] = v;
    reinterpret_cast<__half2*>(g_buf0)[o] =
        __float22half2_rn(make_float2(v.x * c, v.y * c));
}

// One warp per destination node; half2 per lane covers the 64-dim row.
// y_t = r_in[t] * sum_e exp(l_e) * x'_f   where x' carries the r_out factor.
// dst stores fp16(r_out[t] * y_t) for the next layer; acc keeps fp32 y_t.
// MODE 2 (layer 1): acc = emb_row + y
// MODE 0 (middle) : acc += y
// MODE 1 (final)  : acc = (acc + y) * 0.25, no dst
template <int MODE>
__global__ void k_layer(const __half2* __restrict__ src, __half2* __restrict__ dst,
                        float* __restrict__ acc, const float* __restrict__ emb) {
    int warp = (blockIdx.x * blockDim.x + threadIdx.x) >> 5;
    int lane = threadIdx.x & 31;
    if (warp >= N_NODES) return;
    const int2* row = &g_ell[(size_t)warp * MAXDEG];
    int cnt = g_deg[warp];

    float ax = 0.0f, ay = 0.0f;

    int k = 0;
    for (; k + 8 <= cnt; k += 8) {
        #pragma unroll
        for (int i = 0; i < 8; i++) {
            int2 e = __ldg(&row[k + i]);
            float w = __int_as_float(e.y);
            float2 v = __half22float2(__ldg(&src[(size_t)e.x * 32 + lane]));
            ax = fmaf(w, v.x, ax);
            ay = fmaf(w, v.y, ay);
        }
    }
    for (; k < cnt; k++) {
        int2 e = __ldg(&row[k]);
        float w = __int_as_float(e.y);
        float2 v = __half22float2(__ldg(&src[(size_t)e.x * 32 + lane]));
        ax = fmaf(w, v.x, ax);
        ay = fmaf(w, v.y, ay);
    }

    float rin = g_rin[warp];           // broadcast
    ax *= rin; ay *= rin;              // y_t

    size_t o = (size_t)warp * 32 + lane;
    float2* acc2 = reinterpret_cast<float2*>(acc);
    if (MODE != 1) {
        float rout = g_rout[warp];
        dst[o] = __float22half2_rn(make_float2(ax * rout, ay * rout));
    }
    if (MODE == 2) {
        float2 e0 = reinterpret_cast<const float2*>(emb)[o];
        acc2[o] = make_float2(e0.x + ax, e0.y + ay);
    } else if (MODE == 0) {
        float2 av = acc2[o];
        acc2[o] = make_float2(av.x + ax, av.y + ay);
    } else {
        float2 av = acc2[o];
        acc2[o] = make_float2((av.x + ax) * 0.25f, (av.y + ay) * 0.25f);
    }
}

// ---------------- launch ------------------------------------------------------
extern "C" void kernel_launch(void* const* d_in, const int* in_sizes, int n_in,
                              void* d_out, int out_size) {
    const float* emb  = (const float*)d_in[0];   // [N_NODES, 64]
    const int*   ei   = (const int*)d_in[1];     // [2, N_EDGES]
    const float* attr = (const float*)d_in[2];   // [N_EDGES]
    float* out = (float*)d_out;                  // [2 * N_NODES * 64]
    float* acc = out + (size_t)N_NODES * DIM;    // second tuple element

    __half2 *buf0, *bufA, *bufB;
    float *inSum, *outSum;
    int *deg;
    cudaGetSymbolAddress((void**)&buf0,   g_buf0);
    cudaGetSymbolAddress((void**)&bufA,   g_bufA);
    cudaGetSymbolAddress((void**)&bufB,   g_bufB);
    cudaGetSymbolAddress((void**)&inSum,  g_in_sum);
    cudaGetSymbolAddress((void**)&outSum, g_out_sum);
    cudaGetSymbolAddress((void**)&deg,    g_deg);

    const int TB = 256;
    const int grid_edges = (N_EDGES + TB - 1) / TB;
    const int grid_nodes = (N_NODES + TB - 1) / TB;
    const int grid_pre   = (N_NODES * 32 + TB - 1) / TB;
    const int grid_layer = (N_NODES * 32 + 511) / 512;   // warp per node

    // Zero stats
    cudaMemsetAsync(inSum,  0, N_NODES * sizeof(float));
    cudaMemsetAsync(outSum, 0, N_NODES * sizeof(float));
    cudaMemsetAsync(deg,    0, N_NODES * sizeof(int));

    // Fused single edge pass: stats + histogram + ELL placement
    k_edge_build<<<grid_edges, TB>>>(ei, attr);
    // Per-node rsqrt factors, then prescaled fp16 emb + out copy (fused)
    k_rcp<<<grid_nodes, TB>>>();
    k_prescale<<<grid_pre, TB>>>(emb, out);

    // 3 propagation layers (gather formulation, fp16 sources, fp32 accum)
    k_layer<2><<<grid_layer, 512>>>(buf0, bufA, acc, emb);   // acc = emb + l1
    k_layer<0><<<grid_layer, 512>>>(bufA, bufB, acc, emb);   // acc += l2
    k_layer<1><<<grid_layer, 512>>>(bufB, nullptr, acc, emb);// acc = (acc+l3)/4
}

// round 9
// speedup vs baseline: 1.2225x; 1.2225x over previous
#include <cuda_runtime.h>
#include <cuda_fp16.h>
#include <cstdint>

// Problem constants (fixed by the dataset)
#define N_NODES 100000
#define N_EDGES 3200000
#define DIM     64
#define EPS     1e-16f

// ELL row capacity. Destination in-degree ~ Binomial(3.2M, 1e-5) ~ Poisson(32);
// P(deg >= 112) ~ e^-60 per node -- statistically impossible. Row stride
// 112 * 8B = 896B (128B-aligned).
#define MAXDEG  112

// ---------------- device scratch (static globals: allocation-free) ----------
__device__ float  g_in_sum[N_NODES];        // sum exp(l) over incoming edges (by to_)
__device__ float  g_out_sum[N_NODES];       // sum exp(l) over outgoing edges (by from_)
__device__ float  g_rin[N_NODES];           // rsqrt(in_sum + eps)  per node
__device__ float  g_rout[N_NODES];          // rsqrt(out_sum + eps) per node
__device__ float  g_irout[N_NODES];         // sqrt(out_sum + eps) = 1/rout
__device__ int    g_deg[N_NODES];           // in-degree (by to_)
__device__ int2   g_ell[(size_t)N_NODES * MAXDEG];  // {src, exp(l)_bits} padded rows
__device__ __half g_buf0[(size_t)N_NODES * DIM];    // fp16 prescaled emb (rout_f * emb)
__device__ __half g_bufA[(size_t)N_NODES * DIM];    // fp16 scaled layer outputs
__device__ __half g_bufB[(size_t)N_NODES * DIM];

// ---------------- kernels ----------------------------------------------------

// SINGLE fused edge pass: softmax exp-sums for both directions + in-degree
// histogram + direct ELL placement of {src, exp(l)}. Max-subtraction dropped:
// logits ~ N(0,1), exp() cannot overflow; only diff vs reference is the eps.
__global__ void k_edge_build(const int* __restrict__ ei, const float* __restrict__ attr) {
    int e = blockIdx.x * blockDim.x + threadIdx.x;
    if (e >= N_EDGES) return;
    int f = __ldcs(&ei[e]);
    int t = __ldcs(&ei[e + N_EDGES]);
    float el = __expf(__ldcs(&attr[e]));    // s_temp = 1.0
    atomicAdd(&g_in_sum[t],  el);
    atomicAdd(&g_out_sum[f], el);
    int rank = atomicAdd(&g_deg[t], 1);
    if (rank < MAXDEG)                       // impossible overflow guard
        g_ell[(size_t)t * MAXDEG + rank] = make_int2(f, __float_as_int(el));
}

// Per-node scale factors.
__global__ void k_rcp() {
    int i = blockIdx.x * blockDim.x + threadIdx.x;
    if (i >= N_NODES) return;
    float so = g_out_sum[i] + EPS;
    g_rin[i]   = rsqrtf(g_in_sum[i] + EPS);
    g_rout[i]  = rsqrtf(so);
    g_irout[i] = sqrtf(so);
}

// Prescale: out = emb (tuple element 0) and buf0 = fp16(rout_f * emb), one pass.
__global__ void __launch_bounds__(512, 4)
k_prescale(const float* __restrict__ emb, float* __restrict__ out) {
    int o = blockIdx.x * blockDim.x + threadIdx.x;          // float2 index
    if (o >= N_NODES * 32) return;
    int n = o >> 5;
    float c = g_rout[n];                                    // broadcast within row
    float2 v = reinterpret_cast<const float2*>(emb)[o];
    reinterpret_cast<float2*>(out)[o] = v;
    reinterpret_cast<__half2*>(g_buf0)[o] =
        __float22half2_rn(make_float2(v.x * c, v.y * c));
}

// Gather-only propagation layer (layers 1 and 2). One warp per destination
// node; half2 per lane. Stores ONLY fp16(rin*rout * rawsum) -- the carried
// rout factor for the next layer's sources. No acc traffic here.
__global__ void __launch_bounds__(512, 4)
k_gather(const __half2* __restrict__ src, __half2* __restrict__ dst) {
    int warp = (blockIdx.x * blockDim.x + threadIdx.x) >> 5;
    int lane = threadIdx.x & 31;
    if (warp >= N_NODES) return;
    const int2* row = &g_ell[(size_t)warp * MAXDEG];
    int cnt = g_deg[warp];

    float ax0 = 0.f, ay0 = 0.f, ax1 = 0.f, ay1 = 0.f;   // dual accumulators
    int k = 0;
    for (; k + 8 <= cnt; k += 8) {
        #pragma unroll
        for (int i = 0; i < 8; i += 2) {
            int2 e0 = __ldg(&row[k + i]);
            int2 e1 = __ldg(&row[k + i + 1]);
            float2 v0 = __half22float2(__ldg(&src[(size_t)e0.x * 32 + lane]));
            float2 v1 = __half22float2(__ldg(&src[(size_t)e1.x * 32 + lane]));
            float w0 = __int_as_float(e0.y);
            float w1 = __int_as_float(e1.y);
            ax0 = fmaf(w0, v0.x, ax0);  ay0 = fmaf(w0, v0.y, ay0);
            ax1 = fmaf(w1, v1.x, ax1);  ay1 = fmaf(w1, v1.y, ay1);
        }
    }
    for (; k < cnt; k++) {
        int2 e = __ldg(&row[k]);
        float w = __int_as_float(e.y);
        float2 v = __half22float2(__ldg(&src[(size_t)e.x * 32 + lane]));
        ax0 = fmaf(w, v.x, ax0);  ay0 = fmaf(w, v.y, ay0);
    }
    float ax = ax0 + ax1, ay = ay0 + ay1;

    float s = g_rin[warp] * g_rout[warp];   // broadcast; y*rout in one scale
    dst[(size_t)warp * 32 + lane] = __float22half2_rn(make_float2(ax * s, ay * s));
}

// Final layer: gather y3, then reconstruct the full layer-mean:
// acc = (emb + bufA*irout + bufB*irout + y3) * 0.25   (all coalesced reads)
__global__ void __launch_bounds__(512, 4)
k_final(const __half2* __restrict__ src, const __half2* __restrict__ bufA,
        const __half2* __restrict__ bufB, float* __restrict__ acc,
        const float* __restrict__ emb) {
    int warp = (blockIdx.x * blockDim.x + threadIdx.x) >> 5;
    int lane = threadIdx.x & 31;
    if (warp >= N_NODES) return;
    const int2* row = &g_ell[(size_t)warp * MAXDEG];
    int cnt = g_deg[warp];

    float ax0 = 0.f, ay0 = 0.f, ax1 = 0.f, ay1 = 0.f;
    int k = 0;
    for (; k + 8 <= cnt; k += 8) {
        #pragma unroll
        for (int i = 0; i < 8; i += 2) {
            int2 e0 = __ldg(&row[k + i]);
            int2 e1 = __ldg(&row[k + i + 1]);
            float2 v0 = __half22float2(__ldg(&src[(size_t)e0.x * 32 + lane]));
            float2 v1 = __half22float2(__ldg(&src[(size_t)e1.x * 32 + lane]));
            float w0 = __int_as_float(e0.y);
            float w1 = __int_as_float(e1.y);
            ax0 = fmaf(w0, v0.x, ax0);  ay0 = fmaf(w0, v0.y, ay0);
            ax1 = fmaf(w1, v1.x, ax1);  ay1 = fmaf(w1, v1.y, ay1);
        }
    }
    for (; k < cnt; k++) {
        int2 e = __ldg(&row[k]);
        float w = __int_as_float(e.y);
        float2 v = __half22float2(__ldg(&src[(size_t)e.x * 32 + lane]));
        ax0 = fmaf(w, v.x, ax0);  ay0 = fmaf(w, v.y, ay0);
    }
    float rin = g_rin[warp];
    float y3x = (ax0 + ax1) * rin, y3y = (ay0 + ay1) * rin;

    size_t o = (size_t)warp * 32 + lane;
    float ir = g_irout[warp];               // undo the stored rout factor
    float2 a = __half22float2(bufA[o]);
    float2 b = __half22float2(bufB[o]);
    float2 e0 = reinterpret_cast<const float2*>(emb)[o];
    reinterpret_cast<float2*>(acc)[o] = make_float2(
        (e0.x + (a.x + b.x) * ir + y3x) * 0.25f,
        (e0.y + (a.y + b.y) * ir + y3y) * 0.25f);
}

// ---------------- launch ------------------------------------------------------
extern "C" void kernel_launch(void* const* d_in, const int* in_sizes, int n_in,
                              void* d_out, int out_size) {
    const float* emb  = (const float*)d_in[0];   // [N_NODES, 64]
    const int*   ei   = (const int*)d_in[1];     // [2, N_EDGES]
    const float* attr = (const float*)d_in[2];   // [N_EDGES]
    float* out = (float*)d_out;                  // [2 * N_NODES * 64]
    float* acc = out + (size_t)N_NODES * DIM;    // second tuple element

    __half2 *buf0, *bufA, *bufB;
    float *inSum, *outSum;
    int *deg;
    cudaGetSymbolAddress((void**)&buf0,   g_buf0);
    cudaGetSymbolAddress((void**)&bufA,   g_bufA);
    cudaGetSymbolAddress((void**)&bufB,   g_bufB);
    cudaGetSymbolAddress((void**)&inSum,  g_in_sum);
    cudaGetSymbolAddress((void**)&outSum, g_out_sum);
    cudaGetSymbolAddress((void**)&deg,    g_deg);

    const int TB = 256;
    const int grid_edges = (N_EDGES + TB - 1) / TB;
    const int grid_nodes = (N_NODES + TB - 1) / TB;
    const int grid_pre   = (N_NODES * 32 + 511) / 512;
    const int grid_layer = (N_NODES * 32 + 511) / 512;   // warp per node

    // Zero stats
    cudaMemsetAsync(inSum,  0, N_NODES * sizeof(float));
    cudaMemsetAsync(outSum, 0, N_NODES * sizeof(float));
    cudaMemsetAsync(deg,    0, N_NODES * sizeof(int));

    // Fused single edge pass: stats + histogram + ELL placement
    k_edge_build<<<grid_edges, TB>>>(ei, attr);
    // Per-node scale factors, then prescaled fp16 emb + out copy (fused)
    k_rcp<<<grid_nodes, TB>>>();
    k_prescale<<<grid_pre, 512>>>(emb, out);

    // Layers 1-2: gather only, fp16 store. Layer 3: gather + full mean.
    k_gather<<<grid_layer, 512>>>(buf0, bufA);
    k_gather<<<grid_layer, 512>>>(bufA, bufB);
    k_final <<<grid_layer, 512>>>(bufB, bufA, bufB, acc, emb);
}

// round 10
// speedup vs baseline: 1.5580x; 1.2745x over previous
#include <cuda_runtime.h>
#include <cuda_fp16.h>
#include <cstdint>

// Problem constants (fixed by the dataset)
#define N_NODES 100000
#define N_EDGES 3200000
#define DIM     64
#define EPS     1e-16f

// ELL row capacity. In-degree ~ Binomial(3.2M, 1e-5) ~ Poisson(32);
// P(deg >= 104) ~ e^-50 per node. Row stride 112*8B = 896B (128B-aligned).
#define MAXDEG  112

// ---------------- device scratch (static globals: allocation-free) ----------
__device__ float  g_out_sum[N_NODES];       // sum exp(l) over outgoing edges (by from_)
__device__ float  g_rin[N_NODES];           // rsqrt(in_sum + eps)
__device__ float  g_rout[N_NODES];          // rsqrt(out_sum + eps)
__device__ float  g_irout[N_NODES];         // sqrt(out_sum + eps)
__device__ int    g_deg[N_NODES];           // in-degree (by to_)
__device__ int    g_cnt8[N_NODES];          // padded row length (pair-max, mult of 8)
__device__ int2   g_ell[(size_t)N_NODES * MAXDEG];  // {src*16, exp(l)_bits}
__device__ __half g_buf0[(size_t)N_NODES * DIM];    // fp16 rout_f * emb
__device__ __half g_bufA[(size_t)N_NODES * DIM];    // fp16 scaled layer outputs
__device__ __half g_bufB[(size_t)N_NODES * DIM];

// ---------------- kernels ----------------------------------------------------

// Fused edge pass (2 edges/thread): out-softmax exp-sum atomic + in-degree
// rank atomic + ELL placement of {src*16, exp(l)}. in_sum is NOT accumulated
// here -- it's recovered later by summing each ELL row (coalesced, no atomic).
// Max-subtraction dropped: logits ~ N(0,1), exp() cannot overflow.
__global__ void k_edge_build(const int* __restrict__ ei, const float* __restrict__ attr) {
    int i = blockIdx.x * blockDim.x + threadIdx.x;          // edge pair index
    if (i >= N_EDGES / 2) return;
    int2   f2 = __ldcs(reinterpret_cast<const int2*>(ei) + i);
    int2   t2 = __ldcs(reinterpret_cast<const int2*>(ei + N_EDGES) + i);
    float2 l2 = __ldcs(reinterpret_cast<const float2*>(attr) + i);

    float e0 = __expf(l2.x);
    float e1 = __expf(l2.y);
    atomicAdd(&g_out_sum[f2.x], e0);
    atomicAdd(&g_out_sum[f2.y], e1);
    int r0 = atomicAdd(&g_deg[t2.x], 1);
    int r1 = atomicAdd(&g_deg[t2.y], 1);
    if (r0 < MAXDEG) g_ell[(size_t)t2.x * MAXDEG + r0] = make_int2(f2.x * 16, __float_as_int(e0));
    if (r1 < MAXDEG) g_ell[(size_t)t2.y * MAXDEG + r1] = make_int2(f2.y * 16, __float_as_int(e1));
}

// One warp per node: (a) in_sum = sum of own ELL row weights -> rin,
// (b) rout/irout from out_sum, (c) zero-pad row to ceil8(max(deg of warp pair))
// so the paired gather kernels need no bounds checks, (d) publish cnt8.
__global__ void __launch_bounds__(512, 4) k_row_finalize() {
    int warp = (blockIdx.x * blockDim.x + threadIdx.x) >> 5;
    int lane = threadIdx.x & 31;
    if (warp >= N_NODES) return;
    int cnt  = g_deg[warp];
    int pmax = max(cnt, g_deg[warp ^ 1]);                   // gather pairs (2w, 2w+1)
    int cnt8 = min((pmax + 7) & ~7, MAXDEG);

    int2* row = &g_ell[(size_t)warp * MAXDEG];
    float s = 0.0f;
    for (int k = lane; k < cnt; k += 32) s += __int_as_float(row[k].y);
    #pragma unroll
    for (int off = 16; off > 0; off >>= 1) s += __shfl_xor_sync(0xFFFFFFFFu, s, off);

    for (int k = cnt + lane; k < cnt8; k += 32) row[k] = make_int2(0, 0);

    if (lane == 0) {
        float so = g_out_sum[warp] + EPS;
        g_rin[warp]   = rsqrtf(s + EPS);
        g_rout[warp]  = rsqrtf(so);
        g_irout[warp] = sqrtf(so);
        g_cnt8[warp]  = cnt8;
    }
}

// Prescale: out = emb (tuple element 0) and buf0 = fp16(rout_f * emb), one pass.
__global__ void __launch_bounds__(512, 4)
k_prescale(const float* __restrict__ emb, float* __restrict__ out) {
    int o = blockIdx.x * blockDim.x + threadIdx.x;          // float2 index
    if (o >= N_NODES * 32) return;
    int n = o >> 5;
    float c = g_rout[n];
    float2 v = reinterpret_cast<const float2*>(emb)[o];
    reinterpret_cast<float2*>(out)[o] = v;
    reinterpret_cast<__half2*>(g_buf0)[o] =
        __float22half2_rn(make_float2(v.x * c, v.y * c));
}

// Paired gather body: TWO nodes per warp, 16 lanes each (lane covers 4 dims
// via one uint2 = 2x half2). Rows are zero-padded to the pair max, multiple
// of 8 -> single unrolled loop, no predicates, no remainder.
__device__ __forceinline__ void gather_core(
    const uint2* __restrict__ src, const int2* __restrict__ row, int cnt8,
    int l15, float2& a0, float2& a1)
{
    for (int k = 0; k < cnt8; k += 8) {
        #pragma unroll
        for (int i = 0; i < 8; i++) {
            int2 e = __ldg(&row[k + i]);                    // broadcast per half-warp
            uint2 u = __ldg(&src[e.x + l15]);               // e.x premultiplied by 16
            float w = __int_as_float(e.y);
            float2 v0 = __half22float2(*reinterpret_cast<__half2*>(&u.x));
            float2 v1 = __half22float2(*reinterpret_cast<__half2*>(&u.y));
            a0.x = fmaf(w, v0.x, a0.x);  a0.y = fmaf(w, v0.y, a0.y);
            a1.x = fmaf(w, v1.x, a1.x);  a1.y = fmaf(w, v1.y, a1.y);
        }
    }
}

// Layers 1-2: store only fp16(rin*rout * rawsum); no acc traffic.
__global__ void __launch_bounds__(512, 4)
k_gather(const uint2* __restrict__ src, uint2* __restrict__ dst) {
    int gwarp = (blockIdx.x * blockDim.x + threadIdx.x) >> 5;
    if (gwarp >= N_NODES / 2) return;
    int lane = threadIdx.x & 31;
    int node = gwarp * 2 + (lane >> 4);
    int l15  = lane & 15;
    const int2* row = &g_ell[(size_t)node * MAXDEG];
    int cnt8 = g_cnt8[node];

    float2 a0 = make_float2(0.f, 0.f), a1 = make_float2(0.f, 0.f);
    gather_core(src, row, cnt8, l15, a0, a1);

    float s = g_rin[node] * g_rout[node];
    __half2 h0 = __float22half2_rn(make_float2(a0.x * s, a0.y * s));
    __half2 h1 = __float22half2_rn(make_float2(a1.x * s, a1.y * s));
    uint2 o; o.x = *reinterpret_cast<uint32_t*>(&h0); o.y = *reinterpret_cast<uint32_t*>(&h1);
    dst[(size_t)node * 16 + l15] = o;
}

// Final: gather y3, reconstruct acc = (emb + (bufA+bufB)*irout + y3) / 4.
__global__ void __launch_bounds__(512, 4)
k_final(const uint2* __restrict__ src, const uint2* __restrict__ bufA,
        const uint2* __restrict__ bufB, float* __restrict__ acc,
        const float* __restrict__ emb) {
    int gwarp = (blockIdx.x * blockDim.x + threadIdx.x) >> 5;
    if (gwarp >= N_NODES / 2) return;
    int lane = threadIdx.x & 31;
    int node = gwarp * 2 + (lane >> 4);
    int l15  = lane & 15;
    const int2* row = &g_ell[(size_t)node * MAXDEG];
    int cnt8 = g_cnt8[node];

    float2 a0 = make_float2(0.f, 0.f), a1 = make_float2(0.f, 0.f);
    gather_core(src, row, cnt8, l15, a0, a1);

    float rin = g_rin[node];
    float ir  = g_irout[node];
    size_t o = (size_t)node * 16 + l15;
    uint2 ua = bufA[o], ub = bufB[o];
    float2 A0 = __half22float2(*reinterpret_cast<__half2*>(&ua.x));
    float2 A1 = __half22float2(*reinterpret_cast<__half2*>(&ua.y));
    float2 B0 = __half22float2(*reinterpret_cast<__half2*>(&ub.x));
    float2 B1 = __half22float2(*reinterpret_cast<__half2*>(&ub.y));
    float4 e4 = reinterpret_cast<const float4*>(emb)[o];
    float4 r;
    r.x = (e4.x + (A0.x + B0.x) * ir + a0.x * rin) * 0.25f;
    r.y = (e4.y + (A0.y + B0.y) * ir + a0.y * rin) * 0.25f;
    r.z = (e4.z + (A1.x + B1.x) * ir + a1.x * rin) * 0.25f;
    r.w = (e4.w + (A1.y + B1.y) * ir + a1.y * rin) * 0.25f;
    reinterpret_cast<float4*>(acc)[o] = r;
}

// ---------------- launch ------------------------------------------------------
extern "C" void kernel_launch(void* const* d_in, const int* in_sizes, int n_in,
                              void* d_out, int out_size) {
    const float* emb  = (const float*)d_in[0];   // [N_NODES, 64]
    const int*   ei   = (const int*)d_in[1];     // [2, N_EDGES]
    const float* attr = (const float*)d_in[2];   // [N_EDGES]
    float* out = (float*)d_out;                  // [2 * N_NODES * 64]
    float* acc = out + (size_t)N_NODES * DIM;    // second tuple element

    uint2 *buf0, *bufA, *bufB;
    float *outSum;
    int *deg;
    cudaGetSymbolAddress((void**)&buf0,   g_buf0);
    cudaGetSymbolAddress((void**)&bufA,   g_bufA);
    cudaGetSymbolAddress((void**)&bufB,   g_bufB);
    cudaGetSymbolAddress((void**)&outSum, g_out_sum);
    cudaGetSymbolAddress((void**)&deg,    g_deg);

    const int TB = 256;
    const int grid_build = (N_EDGES / 2 + TB - 1) / TB;
    const int grid_fin   = (N_NODES * 32 + 511) / 512;          // warp per node
    const int grid_pre   = (N_NODES * 32 + 511) / 512;
    const int grid_pair  = ((N_NODES / 2) * 32 + 511) / 512;    // warp per node pair

    cudaMemsetAsync(outSum, 0, N_NODES * sizeof(float));
    cudaMemsetAsync(deg,    0, N_NODES * sizeof(int));

    // Build: stats + ELL placement (single edge pass, 2 atomics/edge)
    k_edge_build<<<grid_build, TB>>>(ei, attr);
    // Per-node: in_sum from own row, scale factors, zero-pad to pair max
    k_row_finalize<<<grid_fin, 512>>>();
    // Prescaled fp16 emb + out copy (fused)
    k_prescale<<<grid_pre, 512>>>(emb, out);

    // Layers 1-2: paired gather, fp16 store. Layer 3: paired gather + mean.
    k_gather<<<grid_pair, 512>>>(buf0, bufA);
    k_gather<<<grid_pair, 512>>>(bufA, bufB);
    k_final <<<grid_pair, 512>>>(bufB, bufA, bufB, acc, emb);
}